// round 13
// baseline (speedup 1.0000x reference)
#include <cuda_runtime.h>
#include <cuda_bf16.h>
#include <stdint.h>

// SimpleMovingAverage: history (64, 336, 862, 3) f32.
// window = last Q=12 steps; 336 iterations of m = mean(window), push m.
//
// R12 = R11 with the shared-memory bug fixed: the tile is now ONE dynamic
// extern __shared__ buffer (49.9 KB) shared by all 7 template instantiations
// (R11 declared static __shared__ inside the template -> 7 copies -> 349 KB
// -> ptxas fail). Opt-in via cudaFuncSetAttribute in kernel_launch.
//
// Experiment: remove the scalar store path entirely. Each block computes its
// whole 48-row x 1KB chunk tile into SMEM (no barriers during fill), then
// after ONE __syncthreads + async-proxy fence, 48 lanes issue one
// cp.async.bulk each (16B-aligned via 8B row-phase staging), one commit,
// one wait at block end.
//
// Time split: 7 chunks x 48 steps, templated -> constexpr __constant__
// matrices A^(48c) for chunk entry. Per-step critical path: 1 FFMA:
//   m = s/12;  s = fma(s, 13/12, -w[u]).

#define SMA_Q       12
#define SMA_INLEN   336
#define SMA_OUTLEN  336
#define SMA_ROW     2586          // floats per (b,t) row (10344 B)
#define SMA_ROW2    (SMA_ROW / 2) // 1293 float2
#define SMA_BATCH   64

#define SMA_CHUNKS  7
#define SMA_CSTEPS  (SMA_OUTLEN / SMA_CHUNKS)  // 48 = 4 * 12

#define SMA_W2      128           // float2 lanes per full block (1024 B/row)
#define NFULL       (SMA_ROW2 / SMA_W2)          // 10 full column blocks
#define NPART       (SMA_ROW2 - NFULL * SMA_W2)  // 13 leftover float2
#define TILE_PITCH  1040          // 1024 data + 8 phase + pad (16B multiple)
#define TILE_BYTES  (SMA_CSTEPS * TILE_PITCH)    // 49920

struct SmaMats { float m[SMA_CHUNKS - 1][SMA_Q][SMA_Q]; };

static constexpr SmaMats sma_compute_mats() {
    SmaMats r = {};
    for (int k = 0; k < SMA_Q; k++) {
        float w[SMA_Q] = {};
        for (int i = 0; i < SMA_Q; i++) w[i] = (i == k) ? 1.0f : 0.0f;
        float s = 1.0f;
        for (int c = 0; c < SMA_CHUNKS - 1; c++) {
            for (int t = 0; t < SMA_CSTEPS; t++) {
                int u = t % SMA_Q;
                float mean = s * (1.0f / 12.0f);
                s = s * (13.0f / 12.0f) - w[u];
                w[u] = mean;
            }
            for (int j = 0; j < SMA_Q; j++) r.m[c][k][j] = w[j];
        }
    }
    return r;
}

__constant__ SmaMats c_MATS = sma_compute_mats();

__device__ __forceinline__ uint32_t smem_u32(const void* p) {
    return (uint32_t)__cvta_generic_to_shared(p);
}

template <int CHUNK>
__device__ __forceinline__ void sma_load_window_f2(
    const float2* __restrict__ src, float wx[SMA_Q], float wy[SMA_Q],
    float& sx, float& sy)
{
    sx = 0.0f; sy = 0.0f;
    if (CHUNK == 0) {
#pragma unroll
        for (int k = 0; k < SMA_Q; k++) {
            float2 v = src[(size_t)k * SMA_ROW2];
            wx[k] = v.x; wy[k] = v.y;
            sx += v.x;   sy += v.y;
        }
    } else {
#pragma unroll
        for (int j = 0; j < SMA_Q; j++) { wx[j] = 0.0f; wy[j] = 0.0f; }
#pragma unroll
        for (int k = 0; k < SMA_Q; k++) {
            float2 v = src[(size_t)k * SMA_ROW2];
#pragma unroll
            for (int j = 0; j < SMA_Q; j++) {
                float c = c_MATS.m[CHUNK - 1][k][j];
                wx[j] = fmaf(c, v.x, wx[j]);
                wy[j] = fmaf(c, v.y, wy[j]);
            }
        }
#pragma unroll
        for (int j = 0; j < SMA_Q; j++) { sx += wx[j]; sy += wy[j]; }
    }
}

// ---- full column block: 48-row SMEM tile, single bulk drain ----
template <int CHUNK>
__device__ __forceinline__ void sma_full(const float* __restrict__ in,
                                         float* __restrict__ out,
                                         char* __restrict__ tile)
{
    const int tid   = threadIdx.x;            // 0..127
    const int colf2 = blockIdx.x * SMA_W2;
    const int b     = blockIdx.y;

    const float2* __restrict__ src =
        reinterpret_cast<const float2*>(
            in + (size_t)b * SMA_INLEN * SMA_ROW
               + (size_t)(SMA_INLEN - SMA_Q) * SMA_ROW) + (colf2 + tid);

    float wx[SMA_Q], wy[SMA_Q], sx, sy;
    sma_load_window_f2<CHUNK>(src, wx, wy, sx, sy);

    const float inv_q = 1.0f / 12.0f;
    const float k1312 = 13.0f / 12.0f;

    // ---- fill: all 48 rows into SMEM, no barriers ----
    // Global row (b*336 + CHUNK*48 + r): parity == r&1 == u&1.
    char* trow = tile + tid * 8;
#pragma unroll 1
    for (int blk = 0; blk < SMA_CSTEPS / SMA_Q; blk++) {
#pragma unroll
        for (int u = 0; u < SMA_Q; u++) {
            float mx = sx * inv_q;
            float my = sy * inv_q;
            *reinterpret_cast<float2*>(trow + u * TILE_PITCH + ((u & 1) * 8))
                = make_float2(mx, my);
            sx = fmaf(sx, k1312, -wx[u]);
            sy = fmaf(sy, k1312, -wy[u]);
            wx[u] = mx;
            wy[u] = my;
        }
        trow += SMA_Q * TILE_PITCH;
    }

    asm volatile("fence.proxy.async.shared::cta;" ::: "memory");
    __syncthreads();

    // ---- drain: 48 lanes, one bulk each; odd-row edges by lanes 64..111 ----
    const size_t row0 = (size_t)b * SMA_OUTLEN + (size_t)CHUNK * SMA_CSTEPS;
    char* const outb  = reinterpret_cast<char*>(out) + (size_t)colf2 * 8;

    if (tid < SMA_CSTEPS) {
        const int r = tid;
        char* g  = outb + (row0 + r) * (size_t)(SMA_ROW * 4);
        char* sp = tile + r * TILE_PITCH;
        if ((r & 1) == 0) {
            // even row: fully aligned, 1024 B
            asm volatile(
                "cp.async.bulk.global.shared::cta.bulk_group [%0], [%1], %2;"
                :: "l"(g), "r"(smem_u32(sp)), "r"(1024u) : "memory");
        } else {
            // odd row: data byte D staged at sp+8+D; bulk covers D in [8,1016)
            asm volatile(
                "cp.async.bulk.global.shared::cta.bulk_group [%0], [%1], %2;"
                :: "l"(g + 8), "r"(smem_u32(sp + 16)), "r"(1008u) : "memory");
        }
        asm volatile("cp.async.bulk.commit_group;" ::: "memory");
    } else if (tid >= 64 && tid < 64 + SMA_CSTEPS) {
        // odd-row head+tail patches (2x STG.64 per odd row)
        const int r = tid - 64;
        if (r & 1) {
            char* g  = outb + (row0 + r) * (size_t)(SMA_ROW * 4);
            char* sp = tile + r * TILE_PITCH;
            float2 h = *reinterpret_cast<const float2*>(sp + 8);
            *reinterpret_cast<float2*>(g) = h;
            float2 t = *reinterpret_cast<const float2*>(sp + 8 + 1016);
            *reinterpret_cast<float2*>(g + 1016) = t;
        }
    }

    // block must not exit while bulk copies still read SMEM
    if (tid < SMA_CSTEPS) {
        asm volatile("cp.async.bulk.wait_group.read 0;" ::: "memory");
    }
}

// ---- partial block: 13 float2 lanes, direct stores ----
template <int CHUNK>
__device__ __forceinline__ void sma_part(const float* __restrict__ in,
                                         float* __restrict__ out)
{
    const int tid = threadIdx.x;
    if (tid >= NPART) return;
    const int colf2 = NFULL * SMA_W2;
    const int b     = blockIdx.y;

    const float2* __restrict__ src =
        reinterpret_cast<const float2*>(
            in + (size_t)b * SMA_INLEN * SMA_ROW
               + (size_t)(SMA_INLEN - SMA_Q) * SMA_ROW) + (colf2 + tid);

    float wx[SMA_Q], wy[SMA_Q], sx, sy;
    sma_load_window_f2<CHUNK>(src, wx, wy, sx, sy);

    float2* __restrict__ d =
        reinterpret_cast<float2*>(out + (size_t)b * SMA_OUTLEN * SMA_ROW
                                      + (size_t)CHUNK * SMA_CSTEPS * SMA_ROW)
        + (colf2 + tid);

    const float inv_q = 1.0f / 12.0f;
    const float k1312 = 13.0f / 12.0f;

#pragma unroll 1
    for (int blk = 0; blk < SMA_CSTEPS / SMA_Q; blk++) {
#pragma unroll
        for (int u = 0; u < SMA_Q; u++) {
            float mx = sx * inv_q;
            float my = sy * inv_q;
            d[(size_t)u * SMA_ROW2] = make_float2(mx, my);
            sx = fmaf(sx, k1312, -wx[u]);
            sy = fmaf(sy, k1312, -wy[u]);
            wx[u] = mx;
            wy[u] = my;
        }
        d += (size_t)SMA_Q * SMA_ROW2;
    }
}

template <int CHUNK>
__device__ __forceinline__ void sma_dispatch(const float* __restrict__ in,
                                             float* __restrict__ out,
                                             char* __restrict__ tile)
{
    if (blockIdx.x < NFULL) sma_full<CHUNK>(in, out, tile);
    else                    sma_part<CHUNK>(in, out);
}

__global__ __launch_bounds__(128)
void sma_main_kernel(const float* __restrict__ in, float* __restrict__ out) {
    extern __shared__ __align__(16) char tile[];   // TILE_BYTES dynamic
    switch (blockIdx.z) {
        case 0: sma_dispatch<0>(in, out, tile); break;
        case 1: sma_dispatch<1>(in, out, tile); break;
        case 2: sma_dispatch<2>(in, out, tile); break;
        case 3: sma_dispatch<3>(in, out, tile); break;
        case 4: sma_dispatch<4>(in, out, tile); break;
        case 5: sma_dispatch<5>(in, out, tile); break;
        case 6: sma_dispatch<6>(in, out, tile); break;
        default: break;
    }
}

extern "C" void kernel_launch(void* const* d_in, const int* in_sizes, int n_in,
                              void* d_out, int out_size) {
    (void)in_sizes; (void)n_in; (void)out_size;
    const float* in = (const float*)d_in[0];
    float* out = (float*)d_out;

    // Host-side attribute set: not an allocation, not a stream op;
    // idempotent and safe under graph capture.
    static bool attr_done = false;
    if (!attr_done) {
        cudaFuncSetAttribute(sma_main_kernel,
                             cudaFuncAttributeMaxDynamicSharedMemorySize,
                             TILE_BYTES);
        attr_done = true;
    }

    dim3 grid(NFULL + 1, SMA_BATCH, SMA_CHUNKS);  // (11, 64, 7) = 4928 blocks
    sma_main_kernel<<<grid, 128, TILE_BYTES>>>(in, out);
}

// round 14
// speedup vs baseline: 1.0026x; 1.0026x over previous
#include <cuda_runtime.h>
#include <cuda_bf16.h>
#include <stdint.h>

// SimpleMovingAverage: history (64, 336, 862, 3) f32.
// window = last Q=12 steps; 336 iterations of m = mean(window), push m.
//
// FINAL FORM (R13 = R9, the measured-fastest variant, + tail trim).
// Evidence across R4-R12: five different store mechanisms all pin at
// 45.7-52.6us; 222MB of output / 45.7us = 4.86 TB/s = ~60% of spec, the
// pure-write HBM equilibrium. R9's direct-register float4 path is the floor
// configuration.
//
// Structure:
//  - Time split into 7 chunks x 48 steps (48 = 4*12 keeps the register ring
//    statically indexed). Chunk c rebuilds its start window from the 12
//    input rows via A^(48c): compile-time constexpr matrices in __constant__
//    memory, template-specialized chunk index.
//  - Each thread owns 4 consecutive floats. Row byte-phase is 8*(row&1) and
//    parity is compile-time in the 12-step unroll: even rows -> 1 aligned
//    STG.128, odd rows -> 2 aligned STG.64 (same for input LDG).
//  - Per-step critical path: 1 FFMA per component:
//      m = s/12;  s = fma(s, 13/12, -w[u]).
//  - R13 trim: the 26 leftover floats per row (2586 = 5*512 + 26) are done
//    by ONE block per batch (z==0) running the full 336-step serial scan,
//    instead of 448 nearly-idle per-chunk partial blocks.

#define SMA_Q       12
#define SMA_INLEN   336
#define SMA_OUTLEN  336
#define SMA_ROW     2586          // floats per (b,t) row; 10344 B; %4 == 2
#define SMA_BATCH   64

#define SMA_CHUNKS  7
#define SMA_CSTEPS  (SMA_OUTLEN / SMA_CHUNKS)  // 48 = 4 * 12

#define SMA_W4      128                       // float4 lanes per full block
#define FULLB       5                         // 5*128*4 = 2560 floats covered
#define PART_F2     13                        // (2586-2560)/2 float2 lanes

struct SmaMats { float m[SMA_CHUNKS - 1][SMA_Q][SMA_Q]; };

static constexpr SmaMats sma_compute_mats() {
    SmaMats r = {};
    for (int k = 0; k < SMA_Q; k++) {
        float w[SMA_Q] = {};
        for (int i = 0; i < SMA_Q; i++) w[i] = (i == k) ? 1.0f : 0.0f;
        float s = 1.0f;
        for (int c = 0; c < SMA_CHUNKS - 1; c++) {
            for (int t = 0; t < SMA_CSTEPS; t++) {
                int u = t % SMA_Q;
                float mean = s * (1.0f / 12.0f);
                s = s * (13.0f / 12.0f) - w[u];
                w[u] = mean;
            }
            for (int j = 0; j < SMA_Q; j++) r.m[c][k][j] = w[j];
        }
    }
    return r;
}

__constant__ SmaMats c_MATS = sma_compute_mats();

// ---------------- full blocks: float4 per thread ----------------

template <int CHUNK>
__device__ __forceinline__ void sma_full(const float* __restrict__ in,
                                         float* __restrict__ out)
{
    const int tid = threadIdx.x;
    const int cb  = blockIdx.x;               // 0..FULLB-1
    const int b   = blockIdx.y;
    const int c0  = cb * (SMA_W4 * 4) + tid * 4;   // float index in row, %4==0

    // Input tail rows: row (b*336 + 324 + k), parity == k. SMA_ROW%4==2, so
    // k even -> 16B aligned (LDG.128), k odd -> 8B aligned (2x LDG.64).
    const float* __restrict__ srow =
        in + ((size_t)b * SMA_INLEN + (SMA_INLEN - SMA_Q)) * SMA_ROW + c0;

    float4 w[SMA_Q];
    float4 s;

    if (CHUNK == 0) {
        s = make_float4(0.f, 0.f, 0.f, 0.f);
#pragma unroll
        for (int k = 0; k < SMA_Q; k++) {
            const float* p = srow + (size_t)k * SMA_ROW;
            float4 v;
            if ((k & 1) == 0) {
                v = *reinterpret_cast<const float4*>(p);
            } else {
                float2 a = *reinterpret_cast<const float2*>(p);
                float2 c = *reinterpret_cast<const float2*>(p + 2);
                v = make_float4(a.x, a.y, c.x, c.y);
            }
            w[k] = v;
            s.x += v.x; s.y += v.y; s.z += v.z; s.w += v.w;
        }
    } else {
#pragma unroll
        for (int j = 0; j < SMA_Q; j++) w[j] = make_float4(0.f, 0.f, 0.f, 0.f);
#pragma unroll
        for (int k = 0; k < SMA_Q; k++) {
            const float* p = srow + (size_t)k * SMA_ROW;
            float4 v;
            if ((k & 1) == 0) {
                v = *reinterpret_cast<const float4*>(p);
            } else {
                float2 a = *reinterpret_cast<const float2*>(p);
                float2 c = *reinterpret_cast<const float2*>(p + 2);
                v = make_float4(a.x, a.y, c.x, c.y);
            }
#pragma unroll
            for (int j = 0; j < SMA_Q; j++) {
                float cf = c_MATS.m[CHUNK - 1][k][j];
                w[j].x = fmaf(cf, v.x, w[j].x);
                w[j].y = fmaf(cf, v.y, w[j].y);
                w[j].z = fmaf(cf, v.z, w[j].z);
                w[j].w = fmaf(cf, v.w, w[j].w);
            }
        }
        s = make_float4(0.f, 0.f, 0.f, 0.f);
#pragma unroll
        for (int j = 0; j < SMA_Q; j++) {
            s.x += w[j].x; s.y += w[j].y; s.z += w[j].z; s.w += w[j].w;
        }
    }

    const float inv_q = 1.0f / 12.0f;
    const float k1312 = 13.0f / 12.0f;

    // Output rows: rowbase = b*336 + CHUNK*48 (even) + blk*12 (even) + u,
    // so row parity == u&1 (compile-time in the unrolled loop).
    float* __restrict__ drow =
        out + ((size_t)b * SMA_OUTLEN + (size_t)CHUNK * SMA_CSTEPS) * SMA_ROW + c0;

#pragma unroll 1
    for (int blk = 0; blk < SMA_CSTEPS / SMA_Q; blk++) {
#pragma unroll
        for (int u = 0; u < SMA_Q; u++) {
            float4 m;
            m.x = s.x * inv_q; m.y = s.y * inv_q;
            m.z = s.z * inv_q; m.w = s.w * inv_q;

            float* p = drow + (size_t)u * SMA_ROW;
            if ((u & 1) == 0) {
                *reinterpret_cast<float4*>(p) = m;           // 16B aligned
            } else {
                *reinterpret_cast<float2*>(p)     = make_float2(m.x, m.y);
                *reinterpret_cast<float2*>(p + 2) = make_float2(m.z, m.w);
            }

            s.x = fmaf(s.x, k1312, -w[u].x);
            s.y = fmaf(s.y, k1312, -w[u].y);
            s.z = fmaf(s.z, k1312, -w[u].z);
            s.w = fmaf(s.w, k1312, -w[u].w);
            w[u] = m;
        }
        drow += (size_t)SMA_Q * SMA_ROW;
    }
}

// ---- partial columns: 13 float2 lanes, full 336-step serial scan ----
// One block per batch (launched at z==0 only): replaces 7 per-chunk partial
// blocks with one. 336 = 28*12 keeps the ring statically indexed.

__device__ __forceinline__ void sma_part_serial(const float* __restrict__ in,
                                                float* __restrict__ out)
{
    const int tid = threadIdx.x;
    if (tid >= PART_F2) return;
    const int b  = blockIdx.y;
    const int c0 = FULLB * SMA_W4 * 4 + tid * 2;   // float index, 2560 + 2t

    const float* __restrict__ srow =
        in + ((size_t)b * SMA_INLEN + (SMA_INLEN - SMA_Q)) * SMA_ROW + c0;

    float wx[SMA_Q], wy[SMA_Q];
    float sx = 0.f, sy = 0.f;
#pragma unroll
    for (int k = 0; k < SMA_Q; k++) {
        float2 v = *reinterpret_cast<const float2*>(srow + (size_t)k * SMA_ROW);
        wx[k] = v.x; wy[k] = v.y;
        sx += v.x;   sy += v.y;
    }

    const float inv_q = 1.0f / 12.0f;
    const float k1312 = 13.0f / 12.0f;

    float* __restrict__ drow = out + (size_t)b * SMA_OUTLEN * SMA_ROW + c0;

#pragma unroll 1
    for (int blk = 0; blk < SMA_OUTLEN / SMA_Q; blk++) {   // 28 iterations
#pragma unroll
        for (int u = 0; u < SMA_Q; u++) {
            float mx = sx * inv_q;
            float my = sy * inv_q;
            *reinterpret_cast<float2*>(drow + (size_t)u * SMA_ROW)
                = make_float2(mx, my);
            sx = fmaf(sx, k1312, -wx[u]);
            sy = fmaf(sy, k1312, -wy[u]);
            wx[u] = mx;
            wy[u] = my;
        }
        drow += (size_t)SMA_Q * SMA_ROW;
    }
}

template <int CHUNK>
__device__ __forceinline__ void sma_dispatch(const float* __restrict__ in,
                                             float* __restrict__ out)
{
    if (blockIdx.x < FULLB) {
        sma_full<CHUNK>(in, out);
    } else if (CHUNK == 0) {
        sma_part_serial(in, out);   // only the z==0 layer does the tail cols
    }
}

__global__ __launch_bounds__(128)
void sma_main_kernel(const float* __restrict__ in, float* __restrict__ out) {
    switch (blockIdx.z) {
        case 0: sma_dispatch<0>(in, out); break;
        case 1: sma_dispatch<1>(in, out); break;
        case 2: sma_dispatch<2>(in, out); break;
        case 3: sma_dispatch<3>(in, out); break;
        case 4: sma_dispatch<4>(in, out); break;
        case 5: sma_dispatch<5>(in, out); break;
        case 6: sma_dispatch<6>(in, out); break;
        default: break;
    }
}

extern "C" void kernel_launch(void* const* d_in, const int* in_sizes, int n_in,
                              void* d_out, int out_size) {
    (void)in_sizes; (void)n_in; (void)out_size;
    const float* in = (const float*)d_in[0];
    float* out = (float*)d_out;

    dim3 grid(FULLB + 1, SMA_BATCH, SMA_CHUNKS);  // (6, 64, 7)
    sma_main_kernel<<<grid, 128>>>(in, out);
}

// round 15
// speedup vs baseline: 1.0162x; 1.0136x over previous
#include <cuda_runtime.h>
#include <cuda_bf16.h>
#include <stdint.h>

// SimpleMovingAverage: history (64, 336, 862, 3) f32.
// window = last Q=12 steps; 336 iterations of m = mean(window), push m.
//
// FLOOR CONFIGURATION (R13, fastest measured kernel: 44.7us).
// Evidence R4-R12: six store mechanisms (float2/float4 STG, __stcs,
// SMEM+STG.128, SMEM+UBLKCP bulk) bracket 44.7-52.6us; best = 222MB/44.7us
// = 4.97 TB/s effective writes = pure-write HBM3e equilibrium. R12 falsified
// the store-issue-artifact hypothesis; this is the DRAM write floor.
//
// Structure:
//  - 7 time chunks x 48 steps (48 = 4*12 keeps the register ring statically
//    indexed). Chunk c rebuilds its start window from the 12 input rows via
//    A^(48c): constexpr matrices in __constant__ memory, templated chunk.
//  - Each thread owns 4 consecutive floats. Row byte-phase is 8*(row&1);
//    parity is compile-time in the 12-step unroll: even rows -> 1 aligned
//    STG.128, odd rows -> 2 aligned STG.64 (same split for input LDG).
//  - Per-step critical path: 1 FFMA per component:
//      m = s/12;  s = fma(s, 13/12, -w[u]).
//  - Column tail (26 floats/row) handled by ONE block per batch (z==0)
//    running the full 336-step serial scan.
//  - __launch_bounds__(128, 6): pin the 6-block/SM residency (85 regs x
//    768 thr = 65280 regs <= 64K) against compiler drift.

#define SMA_Q       12
#define SMA_INLEN   336
#define SMA_OUTLEN  336
#define SMA_ROW     2586          // floats per (b,t) row; 10344 B; %4 == 2
#define SMA_BATCH   64

#define SMA_CHUNKS  7
#define SMA_CSTEPS  (SMA_OUTLEN / SMA_CHUNKS)  // 48 = 4 * 12

#define SMA_W4      128                       // float4 lanes per full block
#define FULLB       5                         // 5*128*4 = 2560 floats covered
#define PART_F2     13                        // (2586-2560)/2 float2 lanes

struct SmaMats { float m[SMA_CHUNKS - 1][SMA_Q][SMA_Q]; };

static constexpr SmaMats sma_compute_mats() {
    SmaMats r = {};
    for (int k = 0; k < SMA_Q; k++) {
        float w[SMA_Q] = {};
        for (int i = 0; i < SMA_Q; i++) w[i] = (i == k) ? 1.0f : 0.0f;
        float s = 1.0f;
        for (int c = 0; c < SMA_CHUNKS - 1; c++) {
            for (int t = 0; t < SMA_CSTEPS; t++) {
                int u = t % SMA_Q;
                float mean = s * (1.0f / 12.0f);
                s = s * (13.0f / 12.0f) - w[u];
                w[u] = mean;
            }
            for (int j = 0; j < SMA_Q; j++) r.m[c][k][j] = w[j];
        }
    }
    return r;
}

__constant__ SmaMats c_MATS = sma_compute_mats();

// ---------------- full blocks: float4 per thread ----------------

template <int CHUNK>
__device__ __forceinline__ void sma_full(const float* __restrict__ in,
                                         float* __restrict__ out)
{
    const int tid = threadIdx.x;
    const int cb  = blockIdx.x;               // 0..FULLB-1
    const int b   = blockIdx.y;
    const int c0  = cb * (SMA_W4 * 4) + tid * 4;   // float index in row, %4==0

    // Input tail rows: row (b*336 + 324 + k), parity == k. SMA_ROW%4==2, so
    // k even -> 16B aligned (LDG.128), k odd -> 8B aligned (2x LDG.64).
    const float* __restrict__ srow =
        in + ((size_t)b * SMA_INLEN + (SMA_INLEN - SMA_Q)) * SMA_ROW + c0;

    float4 w[SMA_Q];
    float4 s;

    if (CHUNK == 0) {
        s = make_float4(0.f, 0.f, 0.f, 0.f);
#pragma unroll
        for (int k = 0; k < SMA_Q; k++) {
            const float* p = srow + (size_t)k * SMA_ROW;
            float4 v;
            if ((k & 1) == 0) {
                v = *reinterpret_cast<const float4*>(p);
            } else {
                float2 a = *reinterpret_cast<const float2*>(p);
                float2 c = *reinterpret_cast<const float2*>(p + 2);
                v = make_float4(a.x, a.y, c.x, c.y);
            }
            w[k] = v;
            s.x += v.x; s.y += v.y; s.z += v.z; s.w += v.w;
        }
    } else {
#pragma unroll
        for (int j = 0; j < SMA_Q; j++) w[j] = make_float4(0.f, 0.f, 0.f, 0.f);
#pragma unroll
        for (int k = 0; k < SMA_Q; k++) {
            const float* p = srow + (size_t)k * SMA_ROW;
            float4 v;
            if ((k & 1) == 0) {
                v = *reinterpret_cast<const float4*>(p);
            } else {
                float2 a = *reinterpret_cast<const float2*>(p);
                float2 c = *reinterpret_cast<const float2*>(p + 2);
                v = make_float4(a.x, a.y, c.x, c.y);
            }
#pragma unroll
            for (int j = 0; j < SMA_Q; j++) {
                float cf = c_MATS.m[CHUNK - 1][k][j];
                w[j].x = fmaf(cf, v.x, w[j].x);
                w[j].y = fmaf(cf, v.y, w[j].y);
                w[j].z = fmaf(cf, v.z, w[j].z);
                w[j].w = fmaf(cf, v.w, w[j].w);
            }
        }
        s = make_float4(0.f, 0.f, 0.f, 0.f);
#pragma unroll
        for (int j = 0; j < SMA_Q; j++) {
            s.x += w[j].x; s.y += w[j].y; s.z += w[j].z; s.w += w[j].w;
        }
    }

    const float inv_q = 1.0f / 12.0f;
    const float k1312 = 13.0f / 12.0f;

    // Output rows: rowbase = b*336 + CHUNK*48 (even) + blk*12 (even) + u,
    // so row parity == u&1 (compile-time in the unrolled loop).
    float* __restrict__ drow =
        out + ((size_t)b * SMA_OUTLEN + (size_t)CHUNK * SMA_CSTEPS) * SMA_ROW + c0;

#pragma unroll 1
    for (int blk = 0; blk < SMA_CSTEPS / SMA_Q; blk++) {
#pragma unroll
        for (int u = 0; u < SMA_Q; u++) {
            float4 m;
            m.x = s.x * inv_q; m.y = s.y * inv_q;
            m.z = s.z * inv_q; m.w = s.w * inv_q;

            float* p = drow + (size_t)u * SMA_ROW;
            if ((u & 1) == 0) {
                *reinterpret_cast<float4*>(p) = m;           // 16B aligned
            } else {
                *reinterpret_cast<float2*>(p)     = make_float2(m.x, m.y);
                *reinterpret_cast<float2*>(p + 2) = make_float2(m.z, m.w);
            }

            s.x = fmaf(s.x, k1312, -w[u].x);
            s.y = fmaf(s.y, k1312, -w[u].y);
            s.z = fmaf(s.z, k1312, -w[u].z);
            s.w = fmaf(s.w, k1312, -w[u].w);
            w[u] = m;
        }
        drow += (size_t)SMA_Q * SMA_ROW;
    }
}

// ---- partial columns: 13 float2 lanes, full 336-step serial scan ----
// One block per batch (z==0 only). 336 = 28*12 keeps the ring static.

__device__ __forceinline__ void sma_part_serial(const float* __restrict__ in,
                                                float* __restrict__ out)
{
    const int tid = threadIdx.x;
    if (tid >= PART_F2) return;
    const int b  = blockIdx.y;
    const int c0 = FULLB * SMA_W4 * 4 + tid * 2;   // float index, 2560 + 2t

    const float* __restrict__ srow =
        in + ((size_t)b * SMA_INLEN + (SMA_INLEN - SMA_Q)) * SMA_ROW + c0;

    float wx[SMA_Q], wy[SMA_Q];
    float sx = 0.f, sy = 0.f;
#pragma unroll
    for (int k = 0; k < SMA_Q; k++) {
        float2 v = *reinterpret_cast<const float2*>(srow + (size_t)k * SMA_ROW);
        wx[k] = v.x; wy[k] = v.y;
        sx += v.x;   sy += v.y;
    }

    const float inv_q = 1.0f / 12.0f;
    const float k1312 = 13.0f / 12.0f;

    float* __restrict__ drow = out + (size_t)b * SMA_OUTLEN * SMA_ROW + c0;

#pragma unroll 1
    for (int blk = 0; blk < SMA_OUTLEN / SMA_Q; blk++) {   // 28 iterations
#pragma unroll
        for (int u = 0; u < SMA_Q; u++) {
            float mx = sx * inv_q;
            float my = sy * inv_q;
            *reinterpret_cast<float2*>(drow + (size_t)u * SMA_ROW)
                = make_float2(mx, my);
            sx = fmaf(sx, k1312, -wx[u]);
            sy = fmaf(sy, k1312, -wy[u]);
            wx[u] = mx;
            wy[u] = my;
        }
        drow += (size_t)SMA_Q * SMA_ROW;
    }
}

template <int CHUNK>
__device__ __forceinline__ void sma_dispatch(const float* __restrict__ in,
                                             float* __restrict__ out)
{
    if (blockIdx.x < FULLB) {
        sma_full<CHUNK>(in, out);
    } else if (CHUNK == 0) {
        sma_part_serial(in, out);   // only the z==0 layer does the tail cols
    }
}

__global__ __launch_bounds__(128, 6)
void sma_main_kernel(const float* __restrict__ in, float* __restrict__ out) {
    switch (blockIdx.z) {
        case 0: sma_dispatch<0>(in, out); break;
        case 1: sma_dispatch<1>(in, out); break;
        case 2: sma_dispatch<2>(in, out); break;
        case 3: sma_dispatch<3>(in, out); break;
        case 4: sma_dispatch<4>(in, out); break;
        case 5: sma_dispatch<5>(in, out); break;
        case 6: sma_dispatch<6>(in, out); break;
        default: break;
    }
}

extern "C" void kernel_launch(void* const* d_in, const int* in_sizes, int n_in,
                              void* d_out, int out_size) {
    (void)in_sizes; (void)n_in; (void)out_size;
    const float* in = (const float*)d_in[0];
    float* out = (float*)d_out;

    dim3 grid(FULLB + 1, SMA_BATCH, SMA_CHUNKS);  // (6, 64, 7)
    sma_main_kernel<<<grid, 128>>>(in, out);
}

// round 16
// speedup vs baseline: 1.0532x; 1.0364x over previous
#include <cuda_runtime.h>
#include <cuda_bf16.h>
#include <stdint.h>

// SimpleMovingAverage: history (64, 336, 862, 3) f32.
// window = last Q=12 steps; 336 iterations of m = mean(window), push m.
//
// R15 = R13 floor configuration (fastest measured kernel, 44.7us) with
// evict-first streaming stores. Rationale: the bench's graph-replay steady
// state must drain all 222MB to DRAM every iteration; plain STG leaves
// ~126MB dirty in L2 whose write-back lands in the NEXT replay. __stcs
// (evict-first) drains eagerly and stops cross-replay L2 thrash. The R14
// min-blocks clause is reverted (it degraded ptxas scheduling).
//
// Structure:
//  - 7 time chunks x 48 steps (48 = 4*12 keeps the register ring statically
//    indexed). Chunk c rebuilds its start window from the 12 input rows via
//    A^(48c): constexpr matrices in __constant__ memory, templated chunk.
//  - Each thread owns 4 consecutive floats. Row byte-phase is 8*(row&1);
//    parity is compile-time in the 12-step unroll: even rows -> 1 aligned
//    STG.128.CS, odd rows -> 2 aligned STG.64.CS (same split for input LDG).
//  - Per-step critical path: 1 FFMA per component:
//      m = s/12;  s = fma(s, 13/12, -w[u]).
//  - Column tail (26 floats/row): ONE block per batch (z==0) runs the full
//    336-step serial scan.

#define SMA_Q       12
#define SMA_INLEN   336
#define SMA_OUTLEN  336
#define SMA_ROW     2586          // floats per (b,t) row; 10344 B; %4 == 2
#define SMA_BATCH   64

#define SMA_CHUNKS  7
#define SMA_CSTEPS  (SMA_OUTLEN / SMA_CHUNKS)  // 48 = 4 * 12

#define SMA_W4      128                       // float4 lanes per full block
#define FULLB       5                         // 5*128*4 = 2560 floats covered
#define PART_F2     13                        // (2586-2560)/2 float2 lanes

struct SmaMats { float m[SMA_CHUNKS - 1][SMA_Q][SMA_Q]; };

static constexpr SmaMats sma_compute_mats() {
    SmaMats r = {};
    for (int k = 0; k < SMA_Q; k++) {
        float w[SMA_Q] = {};
        for (int i = 0; i < SMA_Q; i++) w[i] = (i == k) ? 1.0f : 0.0f;
        float s = 1.0f;
        for (int c = 0; c < SMA_CHUNKS - 1; c++) {
            for (int t = 0; t < SMA_CSTEPS; t++) {
                int u = t % SMA_Q;
                float mean = s * (1.0f / 12.0f);
                s = s * (13.0f / 12.0f) - w[u];
                w[u] = mean;
            }
            for (int j = 0; j < SMA_Q; j++) r.m[c][k][j] = w[j];
        }
    }
    return r;
}

__constant__ SmaMats c_MATS = sma_compute_mats();

// ---------------- full blocks: float4 per thread ----------------

template <int CHUNK>
__device__ __forceinline__ void sma_full(const float* __restrict__ in,
                                         float* __restrict__ out)
{
    const int tid = threadIdx.x;
    const int cb  = blockIdx.x;               // 0..FULLB-1
    const int b   = blockIdx.y;
    const int c0  = cb * (SMA_W4 * 4) + tid * 4;   // float index in row, %4==0

    // Input tail rows: row (b*336 + 324 + k), parity == k. SMA_ROW%4==2, so
    // k even -> 16B aligned (LDG.128), k odd -> 8B aligned (2x LDG.64).
    const float* __restrict__ srow =
        in + ((size_t)b * SMA_INLEN + (SMA_INLEN - SMA_Q)) * SMA_ROW + c0;

    float4 w[SMA_Q];
    float4 s;

    if (CHUNK == 0) {
        s = make_float4(0.f, 0.f, 0.f, 0.f);
#pragma unroll
        for (int k = 0; k < SMA_Q; k++) {
            const float* p = srow + (size_t)k * SMA_ROW;
            float4 v;
            if ((k & 1) == 0) {
                v = *reinterpret_cast<const float4*>(p);
            } else {
                float2 a = *reinterpret_cast<const float2*>(p);
                float2 c = *reinterpret_cast<const float2*>(p + 2);
                v = make_float4(a.x, a.y, c.x, c.y);
            }
            w[k] = v;
            s.x += v.x; s.y += v.y; s.z += v.z; s.w += v.w;
        }
    } else {
#pragma unroll
        for (int j = 0; j < SMA_Q; j++) w[j] = make_float4(0.f, 0.f, 0.f, 0.f);
#pragma unroll
        for (int k = 0; k < SMA_Q; k++) {
            const float* p = srow + (size_t)k * SMA_ROW;
            float4 v;
            if ((k & 1) == 0) {
                v = *reinterpret_cast<const float4*>(p);
            } else {
                float2 a = *reinterpret_cast<const float2*>(p);
                float2 c = *reinterpret_cast<const float2*>(p + 2);
                v = make_float4(a.x, a.y, c.x, c.y);
            }
#pragma unroll
            for (int j = 0; j < SMA_Q; j++) {
                float cf = c_MATS.m[CHUNK - 1][k][j];
                w[j].x = fmaf(cf, v.x, w[j].x);
                w[j].y = fmaf(cf, v.y, w[j].y);
                w[j].z = fmaf(cf, v.z, w[j].z);
                w[j].w = fmaf(cf, v.w, w[j].w);
            }
        }
        s = make_float4(0.f, 0.f, 0.f, 0.f);
#pragma unroll
        for (int j = 0; j < SMA_Q; j++) {
            s.x += w[j].x; s.y += w[j].y; s.z += w[j].z; s.w += w[j].w;
        }
    }

    const float inv_q = 1.0f / 12.0f;
    const float k1312 = 13.0f / 12.0f;

    // Output rows: rowbase = b*336 + CHUNK*48 (even) + blk*12 (even) + u,
    // so row parity == u&1 (compile-time in the unrolled loop).
    float* __restrict__ drow =
        out + ((size_t)b * SMA_OUTLEN + (size_t)CHUNK * SMA_CSTEPS) * SMA_ROW + c0;

#pragma unroll 1
    for (int blk = 0; blk < SMA_CSTEPS / SMA_Q; blk++) {
#pragma unroll
        for (int u = 0; u < SMA_Q; u++) {
            float4 m;
            m.x = s.x * inv_q; m.y = s.y * inv_q;
            m.z = s.z * inv_q; m.w = s.w * inv_q;

            float* p = drow + (size_t)u * SMA_ROW;
            if ((u & 1) == 0) {
                __stcs(reinterpret_cast<float4*>(p), m);     // 16B aligned
            } else {
                __stcs(reinterpret_cast<float2*>(p),     make_float2(m.x, m.y));
                __stcs(reinterpret_cast<float2*>(p + 2), make_float2(m.z, m.w));
            }

            s.x = fmaf(s.x, k1312, -w[u].x);
            s.y = fmaf(s.y, k1312, -w[u].y);
            s.z = fmaf(s.z, k1312, -w[u].z);
            s.w = fmaf(s.w, k1312, -w[u].w);
            w[u] = m;
        }
        drow += (size_t)SMA_Q * SMA_ROW;
    }
}

// ---- partial columns: 13 float2 lanes, full 336-step serial scan ----
// One block per batch (z==0 only). 336 = 28*12 keeps the ring static.

__device__ __forceinline__ void sma_part_serial(const float* __restrict__ in,
                                                float* __restrict__ out)
{
    const int tid = threadIdx.x;
    if (tid >= PART_F2) return;
    const int b  = blockIdx.y;
    const int c0 = FULLB * SMA_W4 * 4 + tid * 2;   // float index, 2560 + 2t

    const float* __restrict__ srow =
        in + ((size_t)b * SMA_INLEN + (SMA_INLEN - SMA_Q)) * SMA_ROW + c0;

    float wx[SMA_Q], wy[SMA_Q];
    float sx = 0.f, sy = 0.f;
#pragma unroll
    for (int k = 0; k < SMA_Q; k++) {
        float2 v = *reinterpret_cast<const float2*>(srow + (size_t)k * SMA_ROW);
        wx[k] = v.x; wy[k] = v.y;
        sx += v.x;   sy += v.y;
    }

    const float inv_q = 1.0f / 12.0f;
    const float k1312 = 13.0f / 12.0f;

    float* __restrict__ drow = out + (size_t)b * SMA_OUTLEN * SMA_ROW + c0;

#pragma unroll 1
    for (int blk = 0; blk < SMA_OUTLEN / SMA_Q; blk++) {   // 28 iterations
#pragma unroll
        for (int u = 0; u < SMA_Q; u++) {
            float mx = sx * inv_q;
            float my = sy * inv_q;
            __stcs(reinterpret_cast<float2*>(drow + (size_t)u * SMA_ROW),
                   make_float2(mx, my));
            sx = fmaf(sx, k1312, -wx[u]);
            sy = fmaf(sy, k1312, -wy[u]);
            wx[u] = mx;
            wy[u] = my;
        }
        drow += (size_t)SMA_Q * SMA_ROW;
    }
}

template <int CHUNK>
__device__ __forceinline__ void sma_dispatch(const float* __restrict__ in,
                                             float* __restrict__ out)
{
    if (blockIdx.x < FULLB) {
        sma_full<CHUNK>(in, out);
    } else if (CHUNK == 0) {
        sma_part_serial(in, out);   // only the z==0 layer does the tail cols
    }
}

__global__ __launch_bounds__(128)
void sma_main_kernel(const float* __restrict__ in, float* __restrict__ out) {
    switch (blockIdx.z) {
        case 0: sma_dispatch<0>(in, out); break;
        case 1: sma_dispatch<1>(in, out); break;
        case 2: sma_dispatch<2>(in, out); break;
        case 3: sma_dispatch<3>(in, out); break;
        case 4: sma_dispatch<4>(in, out); break;
        case 5: sma_dispatch<5>(in, out); break;
        case 6: sma_dispatch<6>(in, out); break;
        default: break;
    }
}

extern "C" void kernel_launch(void* const* d_in, const int* in_sizes, int n_in,
                              void* d_out, int out_size) {
    (void)in_sizes; (void)n_in; (void)out_size;
    const float* in = (const float*)d_in[0];
    float* out = (float*)d_out;

    dim3 grid(FULLB + 1, SMA_BATCH, SMA_CHUNKS);  // (6, 64, 7)
    sma_main_kernel<<<grid, 128>>>(in, out);
}

// round 17
// speedup vs baseline: 1.0991x; 1.0436x over previous
#include <cuda_runtime.h>
#include <cuda_bf16.h>
#include <stdint.h>

// SimpleMovingAverage: history (64, 336, 862, 3) f32.
// window = last Q=12 steps; 336 iterations of m = mean(window), push m.
//
// R16 = R15 (best bench, 47.52us: floor config + __stcs) + shuffle-aligned
// odd-row stores. Odd output rows sit at byte-phase 8; previously stored as
// 2x warp-wide STG.64 (6 L1 wavefronts/warp-segment vs 4 for even rows).
// Now: 2 warp shuffles shift lane ownership by 8B so odd rows emit one
// aligned STG.128 per lane (lanes 0..30) plus 8B head (lane 0) and tail
// (lane 31) STG.64s. Store wavefronts -15%; shuffles are off the critical
// FFMA chain. Each warp owns a contiguous 512B row segment, so the exchange
// is warp-local.
//
// Structure (unchanged):
//  - 7 time chunks x 48 steps (48 = 4*12 keeps the register ring statically
//    indexed). Chunk c rebuilds its start window from the 12 input rows via
//    A^(48c): constexpr matrices in __constant__ memory, templated chunk.
//  - Each thread owns 4 consecutive floats; row parity is compile-time in
//    the 12-step unroll. All output stores are __stcs (evict-first).
//  - Per-step critical path: 1 FFMA per component:
//      m = s/12;  s = fma(s, 13/12, -w[u]).
//  - Column tail (26 floats/row): ONE block per batch (z==0), full 336-step
//    serial scan.

#define SMA_Q       12
#define SMA_INLEN   336
#define SMA_OUTLEN  336
#define SMA_ROW     2586          // floats per (b,t) row; 10344 B; %4 == 2
#define SMA_BATCH   64

#define SMA_CHUNKS  7
#define SMA_CSTEPS  (SMA_OUTLEN / SMA_CHUNKS)  // 48 = 4 * 12

#define SMA_W4      128                       // float4 lanes per full block
#define FULLB       5                         // 5*128*4 = 2560 floats covered
#define PART_F2     13                        // (2586-2560)/2 float2 lanes

struct SmaMats { float m[SMA_CHUNKS - 1][SMA_Q][SMA_Q]; };

static constexpr SmaMats sma_compute_mats() {
    SmaMats r = {};
    for (int k = 0; k < SMA_Q; k++) {
        float w[SMA_Q] = {};
        for (int i = 0; i < SMA_Q; i++) w[i] = (i == k) ? 1.0f : 0.0f;
        float s = 1.0f;
        for (int c = 0; c < SMA_CHUNKS - 1; c++) {
            for (int t = 0; t < SMA_CSTEPS; t++) {
                int u = t % SMA_Q;
                float mean = s * (1.0f / 12.0f);
                s = s * (13.0f / 12.0f) - w[u];
                w[u] = mean;
            }
            for (int j = 0; j < SMA_Q; j++) r.m[c][k][j] = w[j];
        }
    }
    return r;
}

__constant__ SmaMats c_MATS = sma_compute_mats();

// ---------------- full blocks: float4 per thread ----------------

template <int CHUNK>
__device__ __forceinline__ void sma_full(const float* __restrict__ in,
                                         float* __restrict__ out)
{
    const int tid  = threadIdx.x;
    const int lane = tid & 31;
    const int cb   = blockIdx.x;               // 0..FULLB-1
    const int b    = blockIdx.y;
    const int c0   = cb * (SMA_W4 * 4) + tid * 4;  // float index in row, %4==0

    // Input tail rows: row (b*336 + 324 + k), parity == k. SMA_ROW%4==2, so
    // k even -> 16B aligned (LDG.128), k odd -> 8B aligned (2x LDG.64).
    const float* __restrict__ srow =
        in + ((size_t)b * SMA_INLEN + (SMA_INLEN - SMA_Q)) * SMA_ROW + c0;

    float4 w[SMA_Q];
    float4 s;

    if (CHUNK == 0) {
        s = make_float4(0.f, 0.f, 0.f, 0.f);
#pragma unroll
        for (int k = 0; k < SMA_Q; k++) {
            const float* p = srow + (size_t)k * SMA_ROW;
            float4 v;
            if ((k & 1) == 0) {
                v = *reinterpret_cast<const float4*>(p);
            } else {
                float2 a = *reinterpret_cast<const float2*>(p);
                float2 c = *reinterpret_cast<const float2*>(p + 2);
                v = make_float4(a.x, a.y, c.x, c.y);
            }
            w[k] = v;
            s.x += v.x; s.y += v.y; s.z += v.z; s.w += v.w;
        }
    } else {
#pragma unroll
        for (int j = 0; j < SMA_Q; j++) w[j] = make_float4(0.f, 0.f, 0.f, 0.f);
#pragma unroll
        for (int k = 0; k < SMA_Q; k++) {
            const float* p = srow + (size_t)k * SMA_ROW;
            float4 v;
            if ((k & 1) == 0) {
                v = *reinterpret_cast<const float4*>(p);
            } else {
                float2 a = *reinterpret_cast<const float2*>(p);
                float2 c = *reinterpret_cast<const float2*>(p + 2);
                v = make_float4(a.x, a.y, c.x, c.y);
            }
#pragma unroll
            for (int j = 0; j < SMA_Q; j++) {
                float cf = c_MATS.m[CHUNK - 1][k][j];
                w[j].x = fmaf(cf, v.x, w[j].x);
                w[j].y = fmaf(cf, v.y, w[j].y);
                w[j].z = fmaf(cf, v.z, w[j].z);
                w[j].w = fmaf(cf, v.w, w[j].w);
            }
        }
        s = make_float4(0.f, 0.f, 0.f, 0.f);
#pragma unroll
        for (int j = 0; j < SMA_Q; j++) {
            s.x += w[j].x; s.y += w[j].y; s.z += w[j].z; s.w += w[j].w;
        }
    }

    const float inv_q = 1.0f / 12.0f;
    const float k1312 = 13.0f / 12.0f;

    // Output rows: rowbase = b*336 + CHUNK*48 (even) + blk*12 (even) + u,
    // so row parity == u&1 (compile-time in the unrolled loop).
    float* __restrict__ drow =
        out + ((size_t)b * SMA_OUTLEN + (size_t)CHUNK * SMA_CSTEPS) * SMA_ROW + c0;

#pragma unroll 1
    for (int blk = 0; blk < SMA_CSTEPS / SMA_Q; blk++) {
#pragma unroll
        for (int u = 0; u < SMA_Q; u++) {
            float4 m;
            m.x = s.x * inv_q; m.y = s.y * inv_q;
            m.z = s.z * inv_q; m.w = s.w * inv_q;

            float* p = drow + (size_t)u * SMA_ROW;
            if ((u & 1) == 0) {
                // even row: 16B aligned
                __stcs(reinterpret_cast<float4*>(p), m);
            } else {
                // odd row (byte-phase 8): shift lane ownership by 8B.
                // lane l stores {m.z, m.w, lane(l+1).m.x, lane(l+1).m.y} at
                // p+2 floats (16B aligned). Lane 0 adds the 8B segment head,
                // lane 31 stores only its own 8B (tail). Warp-local: each
                // warp owns a contiguous 512B span of the row.
                float nx = __shfl_down_sync(0xffffffffu, m.x, 1);
                float ny = __shfl_down_sync(0xffffffffu, m.y, 1);
                if (lane == 0) {
                    __stcs(reinterpret_cast<float2*>(p),
                           make_float2(m.x, m.y));
                }
                if (lane < 31) {
                    __stcs(reinterpret_cast<float4*>(p + 2),
                           make_float4(m.z, m.w, nx, ny));
                } else {
                    __stcs(reinterpret_cast<float2*>(p + 2),
                           make_float2(m.z, m.w));
                }
            }

            s.x = fmaf(s.x, k1312, -w[u].x);
            s.y = fmaf(s.y, k1312, -w[u].y);
            s.z = fmaf(s.z, k1312, -w[u].z);
            s.w = fmaf(s.w, k1312, -w[u].w);
            w[u] = m;
        }
        drow += (size_t)SMA_Q * SMA_ROW;
    }
}

// ---- partial columns: 13 float2 lanes, full 336-step serial scan ----
// One block per batch (z==0 only). 336 = 28*12 keeps the ring static.

__device__ __forceinline__ void sma_part_serial(const float* __restrict__ in,
                                                float* __restrict__ out)
{
    const int tid = threadIdx.x;
    if (tid >= PART_F2) return;
    const int b  = blockIdx.y;
    const int c0 = FULLB * SMA_W4 * 4 + tid * 2;   // float index, 2560 + 2t

    const float* __restrict__ srow =
        in + ((size_t)b * SMA_INLEN + (SMA_INLEN - SMA_Q)) * SMA_ROW + c0;

    float wx[SMA_Q], wy[SMA_Q];
    float sx = 0.f, sy = 0.f;
#pragma unroll
    for (int k = 0; k < SMA_Q; k++) {
        float2 v = *reinterpret_cast<const float2*>(srow + (size_t)k * SMA_ROW);
        wx[k] = v.x; wy[k] = v.y;
        sx += v.x;   sy += v.y;
    }

    const float inv_q = 1.0f / 12.0f;
    const float k1312 = 13.0f / 12.0f;

    float* __restrict__ drow = out + (size_t)b * SMA_OUTLEN * SMA_ROW + c0;

#pragma unroll 1
    for (int blk = 0; blk < SMA_OUTLEN / SMA_Q; blk++) {   // 28 iterations
#pragma unroll
        for (int u = 0; u < SMA_Q; u++) {
            float mx = sx * inv_q;
            float my = sy * inv_q;
            __stcs(reinterpret_cast<float2*>(drow + (size_t)u * SMA_ROW),
                   make_float2(mx, my));
            sx = fmaf(sx, k1312, -wx[u]);
            sy = fmaf(sy, k1312, -wy[u]);
            wx[u] = mx;
            wy[u] = my;
        }
        drow += (size_t)SMA_Q * SMA_ROW;
    }
}

template <int CHUNK>
__device__ __forceinline__ void sma_dispatch(const float* __restrict__ in,
                                             float* __restrict__ out)
{
    if (blockIdx.x < FULLB) {
        sma_full<CHUNK>(in, out);
    } else if (CHUNK == 0) {
        sma_part_serial(in, out);   // only the z==0 layer does the tail cols
    }
}

__global__ __launch_bounds__(128)
void sma_main_kernel(const float* __restrict__ in, float* __restrict__ out) {
    switch (blockIdx.z) {
        case 0: sma_dispatch<0>(in, out); break;
        case 1: sma_dispatch<1>(in, out); break;
        case 2: sma_dispatch<2>(in, out); break;
        case 3: sma_dispatch<3>(in, out); break;
        case 4: sma_dispatch<4>(in, out); break;
        case 5: sma_dispatch<5>(in, out); break;
        case 6: sma_dispatch<6>(in, out); break;
        default: break;
    }
}

extern "C" void kernel_launch(void* const* d_in, const int* in_sizes, int n_in,
                              void* d_out, int out_size) {
    (void)in_sizes; (void)n_in; (void)out_size;
    const float* in = (const float*)d_in[0];
    float* out = (float*)d_out;

    dim3 grid(FULLB + 1, SMA_BATCH, SMA_CHUNKS);  // (6, 64, 7)
    sma_main_kernel<<<grid, 128>>>(in, out);
}